// round 10
// baseline (speedup 1.0000x reference)
#include <cuda_runtime.h>
#include <math.h>

// sym_logm of B SPD 64x64 fp32 matrices.  (Resubmit of R8 — prior bench run
// died in the GB300 broker before producing a verdict; kernel audited for
// barrier-uniformity and mailbox-coherence invariants, no changes needed.)
// Kernel 1: one-sided Hestenes Jacobi, TWO WARPS per matrix (64-thread CTA),
//   ONE column per lane (32 u64 regs). Phase A (mm=1..31): XOR pairs within
//   each warp via buffered shfl_xor (champion sideA). Cross phase (k=0..32):
//   inter-warp pairs through an SMEM mailbox: fetch partner col (16 LDS.128),
//   lane-local dot (full column resident), rotate own, publish if rotated.
//   Identical rotation schedule to the 1-warp champion -> same convergence.
// Kernel 2: out[b] = sum_k w_k g_k g_k^T via scratch P,Q.

#define MAXB 8192
#define NMAT 64
#define FULLM 0xffffffffu
#define TH2 4e-10f          // |apq| > 2e-5*sqrt(np*nq); validated rel_err 6.2e-5
#define CSTR 34             // column stride in u64 (=272B, float4-aligned, bank-spread)
typedef unsigned long long u64;

__device__ float g_P[(size_t)MAXB * NMAT * NMAT];
__device__ float g_Q[(size_t)MAXB * NMAT * NMAT];

__device__ __forceinline__ u64 pk(float lo, float hi) {
    u64 r; asm("mov.b64 %0,{%1,%2};" : "=l"(r) : "f"(lo), "f"(hi)); return r;
}
__device__ __forceinline__ void upk(u64 v, float& lo, float& hi) {
    asm("mov.b64 {%0,%1},%2;" : "=f"(lo), "=f"(hi) : "l"(v));
}
__device__ __forceinline__ u64 fma2_(u64 a, u64 b, u64 c) {
    u64 d; asm("fma.rn.f32x2 %0,%1,%2,%3;" : "=l"(d) : "l"(a), "l"(b), "l"(c)); return d;
}
__device__ __forceinline__ u64 mul2_(u64 a, u64 b) {
    u64 d; asm("mul.rn.f32x2 %0,%1,%2;" : "=l"(d) : "l"(a), "l"(b)); return d;
}

// Phase-A pair-side: buffered single-pass partner fetch via shfl_xor.
__device__ __forceinline__ int sideA(u64* C, float& n, int mm, bool amP)
{
    u64 R[32];
    #pragma unroll
    for (int j = 0; j < 32; ++j) R[j] = __shfl_xor_sync(FULLM, C[j], mm);

    u64 a0 = 0, a1 = 0;
    #pragma unroll
    for (int j = 0; j < 32; j += 2) {
        a0 = fma2_(C[j],   R[j],   a0);
        a1 = fma2_(C[j+1], R[j+1], a1);
    }
    float l0, h0, l1, h1; upk(a0, l0, h0); upk(a1, l1, h1);
    float apq = (l0 + h0) + (l1 + h1);         // bit-identical on both partners
    float pn  = __shfl_xor_sync(FULLM, n, mm);

    bool rot = (apq * apq > TH2 * n * pn);
    int active = (int)__any_sync(FULLM, rot);
    if (active) {
        float c = 1.0f, se = 0.0f;
        if (rot) {
            float np = amP ? n  : pn;
            float nq = amP ? pn : n;
            float th = 0.5f * (nq - np) / apq;
            float t  = copysignf(1.0f, th) / (fabsf(th) + sqrtf(fmaf(th, th, 1.0f)));
            c = rsqrtf(fmaf(t, t, 1.0f));
            float s = t * c;
            se = amP ? -s : s;
            n  = fmaf(amP ? -t : t, apq, n);
        }
        u64 c2 = pk(c, c), se2 = pk(se, se);
        #pragma unroll
        for (int j = 0; j < 32; ++j)
            C[j] = fma2_(c2, C[j], mul2_(se2, R[j]));
    }
    return active;
}

__global__ __launch_bounds__(64) void jacobi2(const float* __restrict__ X, int B)
{
    __shared__ u64   sCol[NMAT * CSTR];   // column mailbox, 272B stride
    __shared__ float sN[NMAT];
    __shared__ int   sAny;

    const int b    = blockIdx.x;
    const int tid  = threadIdx.x;         // 0..63
    const int w    = tid >> 5;            // warp 0: cols 0-31, warp 1: cols 32-63
    const int lane = tid & 31;
    const int myCol = tid;

    // Load own column (X symmetric: column c == row c).
    u64 C[32];
    {
        const float4* x4 = (const float4*)(X + (size_t)b * 4096);
        #pragma unroll
        for (int r = 0; r < 16; ++r) {
            float4 v = x4[myCol * 16 + r];
            C[2*r] = pk(v.x, v.y); C[2*r+1] = pk(v.z, v.w);
        }
    }
    float n;
    {
        u64 a = 0;
        #pragma unroll
        for (int j = 0; j < 32; ++j) a = fma2_(C[j], C[j], a);
        float lo, hi; upk(a, lo, hi); n = lo + hi;
    }

    for (int sweep = 0; sweep < 28; ++sweep) {
        if (tid == 0) sAny = 0;
        int any = 0;

        // ---- Phase A: XOR pairs within each warp (no inter-warp traffic) ----
        #pragma unroll 1
        for (int mm = 1; mm < 32; ++mm) {
            bool amP = (lane < (lane ^ mm));
            any |= sideA(C, n, mm, amP);
        }

        // ---- publish all columns + norms ----
        {
            ulonglong2* dst = (ulonglong2*)(sCol + myCol * CSTR);
            #pragma unroll
            for (int j = 0; j < 16; ++j)
                dst[j] = make_ulonglong2(C[2*j], C[2*j+1]);
            sN[myCol] = n;
        }
        __syncthreads();

        // ---- Cross phase: inter-warp pairs via SMEM mailbox ----
        #pragma unroll 1
        for (int k = 0; k < 32; ++k) {
            const int pcol = (w == 0) ? (32 + ((lane + k) & 31))
                                      : ((lane - k) & 31);
            // fetch partner column + norm
            u64 F[32];
            {
                const ulonglong2* src = (const ulonglong2*)(sCol + pcol * CSTR);
                #pragma unroll
                for (int j = 0; j < 16; ++j) {
                    ulonglong2 v = src[j];
                    F[2*j] = v.x; F[2*j+1] = v.y;
                }
            }
            float pn = sN[pcol];
            __syncthreads();   // all fetches done before anyone republishes

            // lane-local full dot (both sides accumulate in identical order;
            // register copies of non-rotated columns stay bit-identical to the
            // SMEM copies, so both warps reach the same rot verdict)
            u64 a0 = 0, a1 = 0;
            #pragma unroll
            for (int j = 0; j < 32; j += 2) {
                a0 = fma2_(C[j],   F[j],   a0);
                a1 = fma2_(C[j+1], F[j+1], a1);
            }
            float l0, h0, l1, h1; upk(a0, l0, h0); upk(a1, l1, h1);
            float apq = (l0 + h0) + (l1 + h1);

            bool amP = (w == 0);            // cols 0-31 are always p
            bool rot = (apq * apq > TH2 * n * pn);
            if (__any_sync(FULLM, rot)) {
                any = 1;
                float c = 1.0f, se = 0.0f;
                if (rot) {
                    float np = amP ? n  : pn;
                    float nq = amP ? pn : n;
                    float th = 0.5f * (nq - np) / apq;
                    float t  = copysignf(1.0f, th) / (fabsf(th) + sqrtf(fmaf(th, th, 1.0f)));
                    c = rsqrtf(fmaf(t, t, 1.0f));
                    float s = t * c;
                    se = amP ? -s : s;
                    n  = fmaf(amP ? -t : t, apq, n);
                }
                u64 c2 = pk(c, c), se2 = pk(se, se);
                #pragma unroll
                for (int j = 0; j < 32; ++j)
                    C[j] = fma2_(c2, C[j], mul2_(se2, F[j]));
                // republish own column iff it changed
                if (rot) {
                    ulonglong2* dst = (ulonglong2*)(sCol + myCol * CSTR);
                    #pragma unroll
                    for (int j = 0; j < 16; ++j)
                        dst[j] = make_ulonglong2(C[2*j], C[2*j+1]);
                    sN[myCol] = n;
                }
            }
            __syncthreads();   // publishes visible before next fetch
        }

        if (any) sAny = 1;
        __syncthreads();
        int done = (sAny == 0);
        __syncthreads();       // protect sAny before next-sweep reset
        if (done) break;

        // exact norm refresh (kills analytic-carry drift)
        u64 a = 0;
        #pragma unroll
        for (int j = 0; j < 32; ++j) a = fma2_(C[j], C[j], a);
        float lo, hi; upk(a, lo, hi); n = lo + hi;
    }

    // exact norm -> weight w = log(lambda)/lambda^2 = 0.5*log(n)/n
    float e;
    {
        u64 a = 0;
        #pragma unroll
        for (int j = 0; j < 32; ++j) a = fma2_(C[j], C[j], a);
        float lo, hi; upk(a, lo, hi); e = lo + hi;
    }
    float wq = 0.5f * logf(fmaxf(e, 1e-30f)) / e;
    u64 wq2 = pk(wq, wq);

    u64* Pp = (u64*)(g_P + (size_t)b * 4096);
    u64* Qp = (u64*)(g_Q + (size_t)b * 4096);
    #pragma unroll
    for (int j = 0; j < 32; ++j) {
        Pp[myCol * 32 + j] = C[j];
        Qp[myCol * 32 + j] = mul2_(wq2, C[j]);
    }
}

// out[b][i][j] = sum_k P[b][k][i] * Q[b][k][j]
__global__ __launch_bounds__(256) void gram_epilogue(float* __restrict__ out, int B)
{
    __shared__ float Ps[NMAT * NMAT];
    __shared__ float Qs[NMAT * NMAT];
    const int b = blockIdx.x;
    const int tid = threadIdx.x;
    const float* Pb = g_P + (size_t)b * (NMAT * NMAT);
    const float* Qb = g_Q + (size_t)b * (NMAT * NMAT);

    #pragma unroll
    for (int i = tid; i < NMAT * NMAT; i += 256) {
        Ps[i] = Pb[i];
        Qs[i] = Qb[i];
    }
    __syncthreads();

    const int ti = tid >> 6;
    const int tj = tid & 63;
    float acc[16];
    #pragma unroll
    for (int r = 0; r < 16; ++r) acc[r] = 0.0f;

    #pragma unroll 4
    for (int k = 0; k < NMAT; ++k) {
        float qv = Qs[k * NMAT + tj];
        const float4* prow = (const float4*)&Ps[k * NMAT + ti * 16];
        #pragma unroll
        for (int r4 = 0; r4 < 4; ++r4) {
            float4 p = prow[r4];
            acc[4*r4+0] = fmaf(p.x, qv, acc[4*r4+0]);
            acc[4*r4+1] = fmaf(p.y, qv, acc[4*r4+1]);
            acc[4*r4+2] = fmaf(p.z, qv, acc[4*r4+2]);
            acc[4*r4+3] = fmaf(p.w, qv, acc[4*r4+3]);
        }
    }

    float* Ob = out + (size_t)b * (NMAT * NMAT);
    #pragma unroll
    for (int r = 0; r < 16; ++r)
        Ob[(ti * 16 + r) * NMAT + tj] = acc[r];
}

extern "C" void kernel_launch(void* const* d_in, const int* in_sizes, int n_in,
                              void* d_out, int out_size) {
    const float* X = (const float*)d_in[0];
    float* out = (float*)d_out;
    int B = in_sizes[0] / (NMAT * NMAT);
    if (B > MAXB) B = MAXB;
    jacobi2<<<B, 64>>>(X, B);
    gram_epilogue<<<B, 256>>>(out, B);
}

// round 11
// speedup vs baseline: 1.1870x; 1.1870x over previous
#include <cuda_runtime.h>
#include <math.h>

// sym_logm of B SPD 64x64 fp32 matrices.
// Kernel 1: one-sided Hestenes Jacobi, ONE WARP PER BLOCK, 2 columns per lane
//   (C0 = col L, C1 = col L+32) register-resident as u64 (f32x2 pairs).
//   Phase A (mm=1..31): XOR pairing (j, j^mm); buffered single-pass partner
//   fetch reused for dot AND rotation (champion structure, R8 = 4256us).
//   Cross phase (k=0..31): lane-local pairs (C0,C1); C1 ring-shifts per round.
//   R10 deltas: TH2 4e-10 -> 4e-8 (err model: rel_err ~1.9e-4, 5x margin),
//   __fdividef on the angle path, 4-chain dots (halve FMA chain depth).
// Kernel 2: out[b] = sum_k w_k g_k g_k^T via scratch P,Q.

#define MAXB 8192
#define NMAT 64
#define FULLM 0xffffffffu
// rotation threshold on apq^2: |apq| > 2e-4 * sqrt(np*nq)
#define TH2 4e-8f
typedef unsigned long long u64;

__device__ float g_P[(size_t)MAXB * NMAT * NMAT];
__device__ float g_Q[(size_t)MAXB * NMAT * NMAT];

__device__ __forceinline__ u64 pk(float lo, float hi) {
    u64 r; asm("mov.b64 %0,{%1,%2};" : "=l"(r) : "f"(lo), "f"(hi)); return r;
}
__device__ __forceinline__ void upk(u64 v, float& lo, float& hi) {
    asm("mov.b64 {%0,%1},%2;" : "=f"(lo), "=f"(hi) : "l"(v));
}
__device__ __forceinline__ u64 fma2_(u64 a, u64 b, u64 c) {
    u64 d; asm("fma.rn.f32x2 %0,%1,%2,%3;" : "=l"(d) : "l"(a), "l"(b), "l"(c)); return d;
}
__device__ __forceinline__ u64 mul2_(u64 a, u64 b) {
    u64 d; asm("mul.rn.f32x2 %0,%1,%2;" : "=l"(d) : "l"(a), "l"(b)); return d;
}

// Fast, deterministic Jacobi angle from (np, nq, apq). Same inputs -> same
// (c, s) on both pair-sides (MUFU-based ops are deterministic).
__device__ __forceinline__ void angle_(float np, float nq, float apq,
                                       float& c, float& s, float& t)
{
    float th = __fdividef(0.5f * (nq - np), apq);
    t = __fdividef(copysignf(1.0f, th), fabsf(th) + sqrtf(fmaf(th, th, 1.0f)));
    c = rsqrtf(fmaf(t, t, 1.0f));
    s = t * c;
}

// One pair-side of a Phase-A round: buffered single-pass (fetch once, reuse).
__device__ __forceinline__ int sideA(u64* C, float& n, int mm, bool amP)
{
    u64 R[32];
    #pragma unroll
    for (int j = 0; j < 32; ++j) R[j] = __shfl_xor_sync(FULLM, C[j], mm);

    u64 a0 = 0, a1 = 0, a2 = 0, a3 = 0;
    #pragma unroll
    for (int j = 0; j < 32; j += 4) {
        a0 = fma2_(C[j],   R[j],   a0);
        a1 = fma2_(C[j+1], R[j+1], a1);
        a2 = fma2_(C[j+2], R[j+2], a2);
        a3 = fma2_(C[j+3], R[j+3], a3);
    }
    float l0, h0, l1, h1, l2, h2, l3, h3;
    upk(a0, l0, h0); upk(a1, l1, h1); upk(a2, l2, h2); upk(a3, l3, h3);
    float apq = ((l0 + h0) + (l1 + h1)) + ((l2 + h2) + (l3 + h3)); // bit-identical both sides
    float pn  = __shfl_xor_sync(FULLM, n, mm);                     // partner's norm

    bool rot = (apq * apq > TH2 * n * pn);
    int active = (int)__any_sync(FULLM, rot);
    if (active) {
        float c = 1.0f, se = 0.0f;
        if (rot) {
            float np = amP ? n  : pn;
            float nq = amP ? pn : n;
            float cc, ss, t;
            angle_(np, nq, apq, cc, ss, t);
            c  = cc;
            se = amP ? -ss : ss;               // p: c*own - s*other ; q: c*own + s*other
            n  = fmaf(amP ? -t : t, apq, n);
        }
        u64 c2 = pk(c, c), se2 = pk(se, se);
        #pragma unroll
        for (int j = 0; j < 32; ++j)
            C[j] = fma2_(c2, C[j], mul2_(se2, R[j]));   // exact no-op when c=1,se=0
    }
    return active;
}

__global__ __launch_bounds__(32) void jacobi_xor(const float* __restrict__ X, int B)
{
    const int warp = blockIdx.x;
    if (warp >= B) return;
    const int lane = threadIdx.x & 31;

    // C0 = column lane, C1 = column lane+32 (X symmetric: column c == row c).
    u64 C0[32], C1[32];
    {
        const float4* x4 = (const float4*)(X + (size_t)warp * 4096);
        #pragma unroll
        for (int r = 0; r < 16; ++r) {
            float4 v = x4[lane * 16 + r];
            C0[2*r]   = pk(v.x, v.y); C0[2*r+1] = pk(v.z, v.w);
            float4 w = x4[(lane + 32) * 16 + r];
            C1[2*r]   = pk(w.x, w.y); C1[2*r+1] = pk(w.z, w.w);
        }
    }

    float n0, n1;
    {
        u64 a0 = 0, a1 = 0;
        #pragma unroll
        for (int j = 0; j < 32; ++j) { a0 = fma2_(C0[j], C0[j], a0); a1 = fma2_(C1[j], C1[j], a1); }
        float lo, hi; upk(a0, lo, hi); n0 = lo + hi; upk(a1, lo, hi); n1 = lo + hi;
    }

    for (int sweep = 0; sweep < 28; ++sweep) {
        int any = 0;

        // ---- Phase A: XOR pairs within each slot ----
        #pragma unroll 1
        for (int mm = 1; mm < 32; ++mm) {
            bool amP = (lane < (lane ^ mm));
            any |= sideA(C0, n0, mm, amP);
            any |= sideA(C1, n1, mm, amP);
        }

        // ---- Cross phase: lane-local pairs (C0, C1); ring-shift C1 each round ----
        #pragma unroll 1
        for (int k = 0; k < 32; ++k) {
            u64 a0 = 0, a1 = 0, a2 = 0, a3 = 0;
            #pragma unroll
            for (int j = 0; j < 32; j += 4) {
                a0 = fma2_(C0[j],   C1[j],   a0);
                a1 = fma2_(C0[j+1], C1[j+1], a1);
                a2 = fma2_(C0[j+2], C1[j+2], a2);
                a3 = fma2_(C0[j+3], C1[j+3], a3);
            }
            float l0, h0, l1, h1, l2, h2, l3, h3;
            upk(a0, l0, h0); upk(a1, l1, h1); upk(a2, l2, h2); upk(a3, l3, h3);
            float apq = ((l0 + h0) + (l1 + h1)) + ((l2 + h2) + (l3 + h3));

            bool rot = (apq * apq > TH2 * n0 * n1);
            if (__any_sync(FULLM, rot)) {
                float c = 1.0f, s = 0.0f;
                if (rot) {
                    float cc, ss, t;
                    angle_(n0, n1, apq, cc, ss, t);   // C0 is always p (lower index)
                    c = cc; s = ss;
                    n0 = fmaf(-t, apq, n0);
                    n1 = fmaf( t, apq, n1);
                    any = 1;
                }
                u64 c2 = pk(c, c), s2 = pk(s, s), ns2 = pk(-s, -s);
                #pragma unroll
                for (int j = 0; j < 32; ++j) {
                    u64 x = C0[j];
                    C0[j] = fma2_(c2, x, mul2_(ns2, C1[j]));
                    C1[j] = fma2_(s2, x, mul2_(c2,  C1[j]));
                }
            }
            // ring-shift slot-1 column (and its norm) to the previous lane
            #pragma unroll
            for (int j = 0; j < 32; ++j) C1[j] = __shfl_sync(FULLM, C1[j], lane + 1);
            n1 = __shfl_sync(FULLM, n1, lane + 1);
        }

        if (!__any_sync(FULLM, any)) break;

        // exact norm refresh (kills analytic-carry drift)
        u64 a0 = 0, a1 = 0;
        #pragma unroll
        for (int j = 0; j < 32; ++j) { a0 = fma2_(C0[j], C0[j], a0); a1 = fma2_(C1[j], C1[j], a1); }
        float lo, hi; upk(a0, lo, hi); n0 = lo + hi; upk(a1, lo, hi); n1 = lo + hi;
    }

    // exact norms -> weights w = log(lambda)/lambda^2 = 0.5*log(n)/n
    float e0, e1;
    {
        u64 a0 = 0, a1 = 0;
        #pragma unroll
        for (int j = 0; j < 32; ++j) { a0 = fma2_(C0[j], C0[j], a0); a1 = fma2_(C1[j], C1[j], a1); }
        float lo, hi; upk(a0, lo, hi); e0 = lo + hi; upk(a1, lo, hi); e1 = lo + hi;
    }
    float w0 = 0.5f * logf(fmaxf(e0, 1e-30f)) / e0;
    float w1 = 0.5f * logf(fmaxf(e1, 1e-30f)) / e1;
    u64 w02 = pk(w0, w0), w12 = pk(w1, w1);

    // Store P = columns, Q = w * columns. Layout [b][col][row], rows contiguous.
    u64* Pp = (u64*)(g_P + (size_t)warp * 4096);
    u64* Qp = (u64*)(g_Q + (size_t)warp * 4096);
    #pragma unroll
    for (int j = 0; j < 32; ++j) {
        Pp[lane * 32 + j]        = C0[j];  Qp[lane * 32 + j]        = mul2_(w02, C0[j]);
        Pp[(lane + 32) * 32 + j] = C1[j];  Qp[(lane + 32) * 32 + j] = mul2_(w12, C1[j]);
    }
}

// out[b][i][j] = sum_k P[b][k][i] * Q[b][k][j]
__global__ __launch_bounds__(256) void gram_epilogue(float* __restrict__ out, int B)
{
    __shared__ float Ps[NMAT * NMAT];
    __shared__ float Qs[NMAT * NMAT];
    const int b = blockIdx.x;
    const int tid = threadIdx.x;
    const float* Pb = g_P + (size_t)b * (NMAT * NMAT);
    const float* Qb = g_Q + (size_t)b * (NMAT * NMAT);

    #pragma unroll
    for (int i = tid; i < NMAT * NMAT; i += 256) {
        Ps[i] = Pb[i];
        Qs[i] = Qb[i];
    }
    __syncthreads();

    const int ti = tid >> 6;
    const int tj = tid & 63;
    float acc[16];
    #pragma unroll
    for (int r = 0; r < 16; ++r) acc[r] = 0.0f;

    #pragma unroll 4
    for (int k = 0; k < NMAT; ++k) {
        float qv = Qs[k * NMAT + tj];
        const float4* prow = (const float4*)&Ps[k * NMAT + ti * 16];
        #pragma unroll
        for (int r4 = 0; r4 < 4; ++r4) {
            float4 p = prow[r4];
            acc[4*r4+0] = fmaf(p.x, qv, acc[4*r4+0]);
            acc[4*r4+1] = fmaf(p.y, qv, acc[4*r4+1]);
            acc[4*r4+2] = fmaf(p.z, qv, acc[4*r4+2]);
            acc[4*r4+3] = fmaf(p.w, qv, acc[4*r4+3]);
        }
    }

    float* Ob = out + (size_t)b * (NMAT * NMAT);
    #pragma unroll
    for (int r = 0; r < 16; ++r)
        Ob[(ti * 16 + r) * NMAT + tj] = acc[r];
}

extern "C" void kernel_launch(void* const* d_in, const int* in_sizes, int n_in,
                              void* d_out, int out_size) {
    const float* X = (const float*)d_in[0];
    float* out = (float*)d_out;
    int B = in_sizes[0] / (NMAT * NMAT);
    if (B > MAXB) B = MAXB;
    jacobi_xor<<<B, 32>>>(X, B);
    gram_epilogue<<<B, 256>>>(out, B);
}

// round 14
// speedup vs baseline: 1.3748x; 1.1582x over previous
#include <cuda_runtime.h>
#include <math.h>

// sym_logm of B SPD 64x64 fp32 matrices.
// R13 = R11 parking structure with the register cap DEFUSED: the (32,11)
// cap (186 regs) likely forced a catastrophic ptxas spill -> timeout ->
// "container failed twice" on two submissions. Now (32,10) = 204 regs,
// which fits the ~155-195 live estimate without hot-loop spill while still
// lifting occupancy 8 -> 10 warps/SM.
// Kernel 1: one-sided Hestenes Jacobi, ONE WARP PER BLOCK, 2 columns per
//   lane, SMEM PARKING: during Phase A only the active 32-column half is in
//   registers (64) + shfl fetch buffer (64); other half parked in 8.4KB SMEM.
//   Sweep: PhaseA(C0) [C1 parked] -> SMEM swap -> PhaseA(C1) [C0 parked]
//          -> unpark -> cross phase (lane-local pairs, ring-shift).
//   TH2 = 4e-9 (calibrated: rel_err ~1.5-2.5e-4, 4-6x margin).
// Kernel 2: out[b] = sum_k w_k g_k g_k^T via scratch P,Q.

#define MAXB 8192
#define NMAT 64
#define FULLM 0xffffffffu
#define TH2 4e-9f
typedef unsigned long long u64;

__device__ float g_P[(size_t)MAXB * NMAT * NMAT];
__device__ float g_Q[(size_t)MAXB * NMAT * NMAT];

__device__ __forceinline__ u64 pk(float lo, float hi) {
    u64 r; asm("mov.b64 %0,{%1,%2};" : "=l"(r) : "f"(lo), "f"(hi)); return r;
}
__device__ __forceinline__ void upk(u64 v, float& lo, float& hi) {
    asm("mov.b64 {%0,%1},%2;" : "=f"(lo), "=f"(hi) : "l"(v));
}
__device__ __forceinline__ u64 fma2_(u64 a, u64 b, u64 c) {
    u64 d; asm("fma.rn.f32x2 %0,%1,%2,%3;" : "=l"(d) : "l"(a), "l"(b), "l"(c)); return d;
}
__device__ __forceinline__ u64 mul2_(u64 a, u64 b) {
    u64 d; asm("mul.rn.f32x2 %0,%1,%2;" : "=l"(d) : "l"(a), "l"(b)); return d;
}

// Deterministic Jacobi angle: same inputs -> same (c,s) on both pair-sides.
__device__ __forceinline__ void angle_(float np, float nq, float apq,
                                       float& c, float& s, float& t)
{
    float th = __fdividef(0.5f * (nq - np), apq);
    t = __fdividef(copysignf(1.0f, th), fabsf(th) + sqrtf(fmaf(th, th, 1.0f)));
    c = rsqrtf(fmaf(t, t, 1.0f));
    s = t * c;
}

// One pair-side of a Phase-A round: buffered single-pass shfl_xor fetch.
__device__ __forceinline__ int sideA(u64* C, float& n, int mm, bool amP)
{
    u64 R[32];
    #pragma unroll
    for (int j = 0; j < 32; ++j) R[j] = __shfl_xor_sync(FULLM, C[j], mm);

    u64 a0 = 0, a1 = 0, a2 = 0, a3 = 0;
    #pragma unroll
    for (int j = 0; j < 32; j += 4) {
        a0 = fma2_(C[j],   R[j],   a0);
        a1 = fma2_(C[j+1], R[j+1], a1);
        a2 = fma2_(C[j+2], R[j+2], a2);
        a3 = fma2_(C[j+3], R[j+3], a3);
    }
    float l0, h0, l1, h1, l2, h2, l3, h3;
    upk(a0, l0, h0); upk(a1, l1, h1); upk(a2, l2, h2); upk(a3, l3, h3);
    float apq = ((l0 + h0) + (l1 + h1)) + ((l2 + h2) + (l3 + h3));
    float pn  = __shfl_xor_sync(FULLM, n, mm);

    bool rot = (apq * apq > TH2 * n * pn);
    int active = (int)__any_sync(FULLM, rot);
    if (active) {
        float c = 1.0f, se = 0.0f;
        if (rot) {
            float np = amP ? n  : pn;
            float nq = amP ? pn : n;
            float cc, ss, t;
            angle_(np, nq, apq, cc, ss, t);
            c  = cc;
            se = amP ? -ss : ss;
            n  = fmaf(amP ? -t : t, apq, n);
        }
        u64 c2 = pk(c, c), se2 = pk(se, se);
        #pragma unroll
        for (int j = 0; j < 32; ++j)
            C[j] = fma2_(c2, C[j], mul2_(se2, R[j]));   // exact no-op when c=1,se=0
    }
    return active;
}

__global__ __launch_bounds__(32, 10) void jacobi_park(const float* __restrict__ Xg, int B)
{
    __shared__ u64   park[32 * 33];   // addr(j,lane)=j*33+lane : conflict-free
    __shared__ float parkN[32];

    const int b    = blockIdx.x;
    const int lane = threadIdx.x;

    u64 X[32];   // active half-matrix column (starts as C0 = col lane)
    u64 Y[32];   // secondary (only live from unpark to sweep tail)

    // Load C0 -> X; C1 (col lane+32) -> park, computing its norm in passing.
    float nP = 0.0f;
    {
        const float4* x4 = (const float4*)(Xg + (size_t)b * 4096);
        #pragma unroll
        for (int r = 0; r < 16; ++r) {
            float4 v = x4[lane * 16 + r];
            X[2*r] = pk(v.x, v.y); X[2*r+1] = pk(v.z, v.w);
            float4 w = x4[(lane + 32) * 16 + r];
            park[(2*r)   * 33 + lane] = pk(w.x, w.y);
            park[(2*r+1) * 33 + lane] = pk(w.z, w.w);
            nP = fmaf(w.x, w.x, fmaf(w.y, w.y, fmaf(w.z, w.z, fmaf(w.w, w.w, nP))));
        }
        parkN[lane] = nP;
    }
    float nX;
    {
        u64 a = 0;
        #pragma unroll
        for (int j = 0; j < 32; ++j) a = fma2_(X[j], X[j], a);
        float lo, hi; upk(a, lo, hi); nX = lo + hi;
    }
    float nY = 0.0f;

    int sweep = 0;
    for (; sweep < 28; ++sweep) {
        int any = 0;

        // ---- Phase A on C0 (C1 parked) ----
        #pragma unroll 1
        for (int mm = 1; mm < 32; ++mm)
            any |= sideA(X, nX, mm, lane < (lane ^ mm));

        // ---- swap active <-> parked (each lane touches only its own slots) ----
        #pragma unroll
        for (int j = 0; j < 32; ++j) {
            u64 t = park[j * 33 + lane];
            park[j * 33 + lane] = X[j];
            X[j] = t;
        }
        { float t = parkN[lane]; parkN[lane] = nX; nX = t; }

        // ---- Phase A on C1 (C0 parked) ----
        #pragma unroll 1
        for (int mm = 1; mm < 32; ++mm)
            any |= sideA(X, nX, mm, lane < (lane ^ mm));

        // ---- unpark C0 into Y ----
        #pragma unroll
        for (int j = 0; j < 32; ++j) Y[j] = park[j * 33 + lane];
        nY = parkN[lane];

        // ---- Cross phase: lane-local pairs (Y=C0 p-side, X=C1 q-side) ----
        #pragma unroll 1
        for (int k = 0; k < 32; ++k) {
            u64 a0 = 0, a1 = 0, a2 = 0, a3 = 0;
            #pragma unroll
            for (int j = 0; j < 32; j += 4) {
                a0 = fma2_(Y[j],   X[j],   a0);
                a1 = fma2_(Y[j+1], X[j+1], a1);
                a2 = fma2_(Y[j+2], X[j+2], a2);
                a3 = fma2_(Y[j+3], X[j+3], a3);
            }
            float l0, h0, l1, h1, l2, h2, l3, h3;
            upk(a0, l0, h0); upk(a1, l1, h1); upk(a2, l2, h2); upk(a3, l3, h3);
            float apq = ((l0 + h0) + (l1 + h1)) + ((l2 + h2) + (l3 + h3));

            bool rot = (apq * apq > TH2 * nY * nX);
            if (__any_sync(FULLM, rot)) {
                float c = 1.0f, s = 0.0f;
                if (rot) {
                    float cc, ss, t;
                    angle_(nY, nX, apq, cc, ss, t);   // Y (=C0) is p (lower index)
                    c = cc; s = ss;
                    nY = fmaf(-t, apq, nY);
                    nX = fmaf( t, apq, nX);
                    any = 1;
                }
                u64 c2 = pk(c, c), s2 = pk(s, s), ns2 = pk(-s, -s);
                #pragma unroll
                for (int j = 0; j < 32; ++j) {
                    u64 y = Y[j];
                    Y[j] = fma2_(c2, y, mul2_(ns2, X[j]));
                    X[j] = fma2_(s2, y, mul2_(c2,  X[j]));
                }
            }
            // ring-shift q-side column (and its norm) to the previous lane
            #pragma unroll
            for (int j = 0; j < 32; ++j) X[j] = __shfl_sync(FULLM, X[j], lane + 1);
            nX = __shfl_sync(FULLM, nX, lane + 1);
        }

        // exit with Y=C0, X=C1 live in registers
        if (!__any_sync(FULLM, any) || sweep == 27) break;

        // ---- exact norm refresh; park C1, reactivate C0 for next sweep ----
        {
            u64 a = 0, bsum = 0;
            #pragma unroll
            for (int j = 0; j < 32; ++j) { a = fma2_(Y[j], Y[j], a); bsum = fma2_(X[j], X[j], bsum); }
            float lo, hi; upk(a, lo, hi); nY = lo + hi; upk(bsum, lo, hi); nX = lo + hi;
        }
        #pragma unroll
        for (int j = 0; j < 32; ++j) {
            park[j * 33 + lane] = X[j];
            X[j] = Y[j];
        }
        parkN[lane] = nX;
        nX = nY;
    }

    // exact norms -> weights w = log(lambda)/lambda^2 = 0.5*log(n)/n
    float e0, e1;
    {
        u64 a0 = 0, a1 = 0;
        #pragma unroll
        for (int j = 0; j < 32; ++j) { a0 = fma2_(Y[j], Y[j], a0); a1 = fma2_(X[j], X[j], a1); }
        float lo, hi; upk(a0, lo, hi); e0 = lo + hi; upk(a1, lo, hi); e1 = lo + hi;
    }
    float w0 = 0.5f * logf(fmaxf(e0, 1e-30f)) / e0;
    float w1 = 0.5f * logf(fmaxf(e1, 1e-30f)) / e1;
    u64 w02 = pk(w0, w0), w12 = pk(w1, w1);

    // Store P = columns, Q = w * columns. Layout [b][col][row], rows contiguous.
    u64* Pp = (u64*)(g_P + (size_t)b * 4096);
    u64* Qp = (u64*)(g_Q + (size_t)b * 4096);
    #pragma unroll
    for (int j = 0; j < 32; ++j) {
        Pp[lane * 32 + j]        = Y[j];  Qp[lane * 32 + j]        = mul2_(w02, Y[j]);
        Pp[(lane + 32) * 32 + j] = X[j];  Qp[(lane + 32) * 32 + j] = mul2_(w12, X[j]);
    }
}

// out[b][i][j] = sum_k P[b][k][i] * Q[b][k][j]
__global__ __launch_bounds__(256) void gram_epilogue(float* __restrict__ out, int B)
{
    __shared__ float Ps[NMAT * NMAT];
    __shared__ float Qs[NMAT * NMAT];
    const int b = blockIdx.x;
    const int tid = threadIdx.x;
    const float* Pb = g_P + (size_t)b * (NMAT * NMAT);
    const float* Qb = g_Q + (size_t)b * (NMAT * NMAT);

    #pragma unroll
    for (int i = tid; i < NMAT * NMAT; i += 256) {
        Ps[i] = Pb[i];
        Qs[i] = Qb[i];
    }
    __syncthreads();

    const int ti = tid >> 6;
    const int tj = tid & 63;
    float acc[16];
    #pragma unroll
    for (int r = 0; r < 16; ++r) acc[r] = 0.0f;

    #pragma unroll 4
    for (int k = 0; k < NMAT; ++k) {
        float qv = Qs[k * NMAT + tj];
        const float4* prow = (const float4*)&Ps[k * NMAT + ti * 16];
        #pragma unroll
        for (int r4 = 0; r4 < 4; ++r4) {
            float4 p = prow[r4];
            acc[4*r4+0] = fmaf(p.x, qv, acc[4*r4+0]);
            acc[4*r4+1] = fmaf(p.y, qv, acc[4*r4+1]);
            acc[4*r4+2] = fmaf(p.z, qv, acc[4*r4+2]);
            acc[4*r4+3] = fmaf(p.w, qv, acc[4*r4+3]);
        }
    }

    float* Ob = out + (size_t)b * (NMAT * NMAT);
    #pragma unroll
    for (int r = 0; r < 16; ++r)
        Ob[(ti * 16 + r) * NMAT + tj] = acc[r];
}

extern "C" void kernel_launch(void* const* d_in, const int* in_sizes, int n_in,
                              void* d_out, int out_size) {
    const float* X = (const float*)d_in[0];
    float* out = (float*)d_out;
    int B = in_sizes[0] / (NMAT * NMAT);
    if (B > MAXB) B = MAXB;
    jacobi_park<<<B, 32>>>(X, B);
    gram_epilogue<<<B, 256>>>(out, B);
}